// round 1
// baseline (speedup 1.0000x reference)
#include <cuda_runtime.h>
#include <math.h>

#define SS 64      // source length
#define BB 32      // batch
#define UU 512     // hidden
#define GG 1536    // 3*U
#define EE 300     // embed dim
#define AD 512     // attention dim
#define VTT 30000  // target vocab
#define TT 32      // target length
#define TM1 31     // T-1 decode steps
#define FF 1836    // 3U + E  (logits feature dim)
#define KX 1324    // 2U + E  (decoder GRU input dim)
#define H2 1024    // 2U

// ---------------- device scratch (static, no allocation) ----------------
__device__ float g_emb_s[SS*BB*EE];
__device__ float g_gi_f[SS*BB*GG];
__device__ float g_gi_b[SS*BB*GG];
__device__ float g_outs_f[SS*BB*UU];
__device__ float g_outs_b[SS*BB*UU];
__device__ float g_h[2][2][BB*UU];          // [dir][parity]
__device__ float g_ghp[2][4][BB*GG];        // encoder gh split-K partials
__device__ float g_enc[BB*SS*H2];           // enc_bt (b,s,2U)
__device__ float g_hfb[BB*H2];
__device__ float g_state[2][BB*UU];         // decoder state ping-pong
__device__ float g_encproj[BB*SS*AD];
__device__ float g_embt[TM1*BB*EE];
__device__ float g_ctx[BB*H2];
__device__ float g_dgp[2][4][BB*GG];        // decoder gi/gh split-K partials
__device__ float g_feat[(long)TM1*BB*FF];

__device__ __forceinline__ float sigm(float x) { return 1.0f / (1.0f + expf(-x)); }

// ---------------- tiny utility kernels ----------------
__global__ void k_zero(float* p, int n) {
    int i = blockIdx.x * blockDim.x + threadIdx.x;
    if (i < n) p[i] = 0.0f;
}

__global__ void k_gather_src(const float* __restrict__ emb, const int* __restrict__ src) {
    int idx = blockIdx.x * blockDim.x + threadIdx.x;
    if (idx >= SS*BB*EE) return;
    int e = idx % EE; int tb = idx / EE;
    g_emb_s[idx] = emb[(long)src[tb]*EE + e];
}

__global__ void k_gather_trg(const float* __restrict__ emb, const int* __restrict__ trg) {
    int idx = blockIdx.x * blockDim.x + threadIdx.x;
    if (idx >= TM1*BB*EE) return;
    int e = idx % EE; int tb = idx / EE;
    g_embt[idx] = emb[(long)trg[tb]*EE + e];
}

// ---------------- generic tiled fp32 GEMM: C = act(A @ W^T + bias) ----------------
// A: [M, lda] (uses cols 0..K-1), W: [N, ldw] (uses cols woff..woff+K-1)
// tile 64x64x16, 256 threads, 4x4 microtile
__global__ void k_gemm(const float* __restrict__ Ap, int lda,
                       const float* __restrict__ Wp, int ldw, int woff,
                       const float* __restrict__ bias,
                       float* __restrict__ Cp, int ldc,
                       int M, int N, int K, int act)
{
    __shared__ float sA[16][64];
    __shared__ float sW[16][64];
    int tid = threadIdx.x;
    int m0 = blockIdx.y * 64, n0 = blockIdx.x * 64;
    int tm = tid & 15, tn = tid >> 4;
    float acc[4][4] = {};
    int row = tid >> 2;          // 0..63
    int kk0 = (tid & 3) * 4;     // 0,4,8,12

    for (int k0 = 0; k0 < K; k0 += 16) {
        #pragma unroll
        for (int j = 0; j < 4; j++) {
            int k = k0 + kk0 + j;
            int m = m0 + row;
            sA[kk0+j][row] = (m < M && k < K) ? Ap[(long)m*lda + k] : 0.0f;
            int n = n0 + row;
            sW[kk0+j][row] = (n < N && k < K) ? Wp[(long)n*ldw + woff + k] : 0.0f;
        }
        __syncthreads();
        #pragma unroll
        for (int kk = 0; kk < 16; kk++) {
            float4 a4 = *reinterpret_cast<const float4*>(&sA[kk][tm*4]);
            float4 b4 = *reinterpret_cast<const float4*>(&sW[kk][tn*4]);
            float av[4] = {a4.x, a4.y, a4.z, a4.w};
            float bv[4] = {b4.x, b4.y, b4.z, b4.w};
            #pragma unroll
            for (int i = 0; i < 4; i++)
                #pragma unroll
                for (int j = 0; j < 4; j++)
                    acc[i][j] = fmaf(av[i], bv[j], acc[i][j]);
        }
        __syncthreads();
    }
    #pragma unroll
    for (int i = 0; i < 4; i++) {
        int m = m0 + tm*4 + i;
        if (m >= M) continue;
        #pragma unroll
        for (int j = 0; j < 4; j++) {
            int n = n0 + tn*4 + j;
            if (n >= N) continue;
            float c = acc[i][j] + (bias ? bias[n] : 0.0f);
            if (act) c = tanhf(c);
            Cp[(long)m*ldc + n] = c;
        }
    }
}

// ---------------- encoder recurrent step: gh partials (split-K) ----------------
// grid (24, 4, 2): x=n-tile, y=k-chunk(128), z=dir. gh[b,n] = sum_k h[b,k]*Whh[n,k]
__global__ void k_enc_gh(const float* __restrict__ Whh_f, const float* __restrict__ Whh_b, int par)
{
    __shared__ float sA[16][32];
    __shared__ float sW[16][64];
    int dir = blockIdx.z, kc = blockIdx.y;
    int n0 = blockIdx.x * 64;
    const float* W = dir ? Whh_b : Whh_f;
    const float* h = g_h[dir][par];
    int tid = threadIdx.x;
    int tm = tid & 15, tn = tid >> 4;
    float acc[2][4] = {};
    int kbase = kc * 128;

    for (int k0 = 0; k0 < 128; k0 += 16) {
        if (tid < 128) {
            int r = tid >> 2, kq = (tid & 3) * 4;
            #pragma unroll
            for (int j = 0; j < 4; j++)
                sA[kq+j][r] = h[r*UU + kbase + k0 + kq + j];
        }
        {
            int r = tid >> 2, kq = (tid & 3) * 4;
            #pragma unroll
            for (int j = 0; j < 4; j++)
                sW[kq+j][r] = W[(long)(n0+r)*UU + kbase + k0 + kq + j];
        }
        __syncthreads();
        #pragma unroll
        for (int kk = 0; kk < 16; kk++) {
            float2 a2 = *reinterpret_cast<const float2*>(&sA[kk][tm*2]);
            float4 b4 = *reinterpret_cast<const float4*>(&sW[kk][tn*4]);
            acc[0][0] = fmaf(a2.x, b4.x, acc[0][0]);
            acc[0][1] = fmaf(a2.x, b4.y, acc[0][1]);
            acc[0][2] = fmaf(a2.x, b4.z, acc[0][2]);
            acc[0][3] = fmaf(a2.x, b4.w, acc[0][3]);
            acc[1][0] = fmaf(a2.y, b4.x, acc[1][0]);
            acc[1][1] = fmaf(a2.y, b4.y, acc[1][1]);
            acc[1][2] = fmaf(a2.y, b4.z, acc[1][2]);
            acc[1][3] = fmaf(a2.y, b4.w, acc[1][3]);
        }
        __syncthreads();
    }
    float* out = &g_ghp[dir][kc][0];
    #pragma unroll
    for (int i = 0; i < 2; i++) {
        int b = tm*2 + i;
        #pragma unroll
        for (int j = 0; j < 4; j++)
            out[b*GG + n0 + tn*4 + j] = acc[i][j];
    }
}

// fused GRU gate update for both directions; writes h[par^1] and outs
__global__ void k_enc_gate(int tf, int tb, int par,
                           const float* __restrict__ bhh_f, const float* __restrict__ bhh_b)
{
    int idx = blockIdx.x * blockDim.x + threadIdx.x;
    if (idx >= 2*BB*UU) return;
    int u = idx & 511;
    int b = (idx >> 9) & 31;
    int dir = idx >> 14;
    const float* gi = dir ? (g_gi_b + (long)tb*BB*GG) : (g_gi_f + (long)tf*BB*GG);
    const float* bhh = dir ? bhh_b : bhh_f;
    float ghr = bhh[u], ghz = bhh[u+UU], ghn = bhh[u+2*UU];
    #pragma unroll
    for (int kc = 0; kc < 4; kc++) {
        const float* p = &g_ghp[dir][kc][b*GG];
        ghr += p[u]; ghz += p[u+UU]; ghn += p[u+2*UU];
    }
    float ir = gi[b*GG + u], iz = gi[b*GG + u + UU], inn = gi[b*GG + u + 2*UU];
    float r = sigm(ir + ghr);
    float z = sigm(iz + ghz);
    float n = tanhf(inn + r*ghn);
    float hp = g_h[dir][par][b*UU + u];
    float hn_ = (1.0f - z)*n + z*hp;
    g_h[dir][par^1][b*UU + u] = hn_;
    float* outs = dir ? (g_outs_b + (long)tb*BB*UU) : (g_outs_f + (long)tf*BB*UU);
    outs[b*UU + u] = hn_;
}

__global__ void k_concat_enc() {
    int idx = blockIdx.x * blockDim.x + threadIdx.x;
    if (idx >= BB*SS*H2) return;
    int h = idx % H2; int bs = idx / H2;
    int s = bs % SS, b = bs / SS;
    float v = (h < UU) ? g_outs_f[((long)s*BB + b)*UU + h]
                       : g_outs_b[((long)s*BB + b)*UU + h - UU];
    g_enc[idx] = v;
}

__global__ void k_concat_hfb() {
    int idx = blockIdx.x * blockDim.x + threadIdx.x;
    if (idx >= BB*H2) return;
    int h = idx % H2; int b = idx / H2;
    float v = (h < UU) ? g_outs_f[((long)(SS-1)*BB + b)*UU + h]
                       : g_outs_b[(long)b*UU + h - UU];
    g_hfb[idx] = v;
}

// ---------------- decoder attention (fused per batch element) ----------------
__global__ void k_dec_attn(int spar, const float* __restrict__ attn_W)
{
    int b = blockIdx.x;
    int tid = threadIdx.x;
    __shared__ float s_st[UU];
    __shared__ float s_tp[AD];
    __shared__ float s_sc[SS];
    __shared__ float s_red[2];

    const float* st = &g_state[spar][b*UU];
    for (int i = tid; i < UU; i += 256) s_st[i] = st[i];
    __syncthreads();

    // st_proj[a] = st . attn_W[a, 0:U]
    for (int a = tid; a < AD; a += 256) {
        const float* w = attn_W + (long)a*GG;
        float acc = 0.0f;
        #pragma unroll 4
        for (int k = 0; k < UU; k += 4) {
            float4 wv = *reinterpret_cast<const float4*>(w + k);
            acc = fmaf(s_st[k],   wv.x, acc);
            acc = fmaf(s_st[k+1], wv.y, acc);
            acc = fmaf(s_st[k+2], wv.z, acc);
            acc = fmaf(s_st[k+3], wv.w, acc);
        }
        s_tp[a] = acc;
    }
    __syncthreads();

    // scores[s] = sum_a tanh(st_proj[a] + encproj[b,s,a]); 4 threads per s
    {
        int s = tid >> 2, q = tid & 3;
        const float* ep = g_encproj + ((long)b*SS + s)*AD + q*128;
        const float* tp = s_tp + q*128;
        float partial = 0.0f;
        for (int a = 0; a < 128; a++) partial += tanhf(tp[a] + ep[a]);
        partial += __shfl_down_sync(0xffffffffu, partial, 2);
        partial += __shfl_down_sync(0xffffffffu, partial, 1);
        if (q == 0) s_sc[s] = partial;
    }
    __syncthreads();
    if (tid == 0) {
        float mx = s_sc[0];
        for (int s = 1; s < SS; s++) mx = fmaxf(mx, s_sc[s]);
        s_red[0] = mx;
    }
    __syncthreads();
    if (tid < SS) s_sc[tid] = expf(s_sc[tid] - s_red[0]);
    __syncthreads();
    if (tid == 0) {
        float sm = 0.0f;
        for (int s = 0; s < SS; s++) sm += s_sc[s];
        s_red[1] = 1.0f / sm;
    }
    __syncthreads();
    float inv = s_red[1];
    // ctx[h] = sum_s w[s] * enc[b,s,h]
    for (int h = tid; h < H2; h += 256) {
        const float* e = g_enc + (long)b*SS*H2 + h;
        float acc = 0.0f;
        #pragma unroll 8
        for (int s = 0; s < SS; s++) acc = fmaf(s_sc[s], e[(long)s*H2], acc);
        g_ctx[b*H2 + h] = acc * inv;
    }
}

// ---------------- decoder GRU matmuls (split-K): z=0 gi (K=1324), z=1 gh (K=512) ----------------
__global__ void k_dec_gemm(int spar, int t,
                           const float* __restrict__ Wih, const float* __restrict__ Whh)
{
    __shared__ float sA[16][32];
    __shared__ float sW[16][64];
    int z = blockIdx.z, kc = blockIdx.y;
    int n0 = blockIdx.x * 64;
    int tid = threadIdx.x;
    int tm = tid & 15, tn = tid >> 4;
    float acc[2][4] = {};
    int K = z ? UU : KX;
    const float* W = z ? Whh : Wih;
    int kchunk = z ? 128 : 332;
    int kbeg = kc * kchunk;
    int kend = min(K, kbeg + kchunk);
    const float* st = g_state[spar];
    const float* em = g_embt + (long)t*BB*EE;

    for (int k0 = kbeg; k0 < kend; k0 += 16) {
        if (tid < 128) {
            int r = tid >> 2, kq = (tid & 3) * 4;
            #pragma unroll
            for (int j = 0; j < 4; j++) {
                int k = k0 + kq + j;
                float v = 0.0f;
                if (k < kend) {
                    if (z) v = st[r*UU + k];
                    else   v = (k < EE) ? em[r*EE + k] : g_ctx[r*H2 + k - EE];
                }
                sA[kq+j][r] = v;
            }
        }
        {
            int r = tid >> 2, kq = (tid & 3) * 4;
            #pragma unroll
            for (int j = 0; j < 4; j++) {
                int k = k0 + kq + j;
                sW[kq+j][r] = (k < kend) ? W[(long)(n0+r)*K + k] : 0.0f;
            }
        }
        __syncthreads();
        #pragma unroll
        for (int kk = 0; kk < 16; kk++) {
            float2 a2 = *reinterpret_cast<const float2*>(&sA[kk][tm*2]);
            float4 b4 = *reinterpret_cast<const float4*>(&sW[kk][tn*4]);
            acc[0][0] = fmaf(a2.x, b4.x, acc[0][0]);
            acc[0][1] = fmaf(a2.x, b4.y, acc[0][1]);
            acc[0][2] = fmaf(a2.x, b4.z, acc[0][2]);
            acc[0][3] = fmaf(a2.x, b4.w, acc[0][3]);
            acc[1][0] = fmaf(a2.y, b4.x, acc[1][0]);
            acc[1][1] = fmaf(a2.y, b4.y, acc[1][1]);
            acc[1][2] = fmaf(a2.y, b4.z, acc[1][2]);
            acc[1][3] = fmaf(a2.y, b4.w, acc[1][3]);
        }
        __syncthreads();
    }
    float* out = &g_dgp[z][kc][0];
    #pragma unroll
    for (int i = 0; i < 2; i++) {
        int b = tm*2 + i;
        #pragma unroll
        for (int j = 0; j < 4; j++)
            out[b*GG + n0 + tn*4 + j] = acc[i][j];
    }
}

// decoder gate + feature row assembly [st2, ctx, emb_t]
__global__ void k_dec_gate(int spar, int t,
                           const float* __restrict__ bih, const float* __restrict__ bhh)
{
    int idx = blockIdx.x * blockDim.x + threadIdx.x;
    if (idx >= BB*FF) return;
    int f = idx % FF; int b = idx / FF;
    float* feat = g_feat + ((long)t*BB + b)*FF;
    if (f < UU) {
        int u = f;
        float gir = bih[u], giz = bih[u+UU], gin = bih[u+2*UU];
        float ghr = bhh[u], ghz = bhh[u+UU], ghn = bhh[u+2*UU];
        #pragma unroll
        for (int kc = 0; kc < 4; kc++) {
            const float* pi = &g_dgp[0][kc][b*GG];
            const float* ph = &g_dgp[1][kc][b*GG];
            gir += pi[u]; giz += pi[u+UU]; gin += pi[u+2*UU];
            ghr += ph[u]; ghz += ph[u+UU]; ghn += ph[u+2*UU];
        }
        float r = sigm(gir + ghr);
        float z = sigm(giz + ghz);
        float n = tanhf(gin + r*ghn);
        float hp = g_state[spar][b*UU + u];
        float h2 = (1.0f - z)*n + z*hp;
        g_state[spar^1][b*UU + u] = h2;
        feat[u] = h2;
    } else if (f < UU + H2) {
        feat[f] = g_ctx[b*H2 + f - UU];
    } else {
        feat[f] = g_embt[((long)t*BB + b)*EE + f - UU - H2];
    }
}

// ---------------- host launch ----------------
static float* symaddr(const void* sym) {
    void* p = nullptr;
    cudaGetSymbolAddress(&p, sym);
    return (float*)p;
}

extern "C" void kernel_launch(void* const* d_in, const int* in_sizes, int n_in,
                              void* d_out, int out_size)
{
    const float* emb_src   = (const float*)d_in[0];
    const float* emb_trg   = (const float*)d_in[1];
    const float* enc_Wih_f = (const float*)d_in[2];
    const float* enc_Whh_f = (const float*)d_in[3];
    const float* enc_bih_f = (const float*)d_in[4];
    const float* enc_bhh_f = (const float*)d_in[5];
    const float* enc_Wih_b = (const float*)d_in[6];
    const float* enc_Whh_b = (const float*)d_in[7];
    const float* enc_bih_b = (const float*)d_in[8];
    const float* enc_bhh_b = (const float*)d_in[9];
    const float* enc_Wfc   = (const float*)d_in[10];
    const float* enc_bfc   = (const float*)d_in[11];
    const float* attn_W    = (const float*)d_in[12];
    const float* attn_b    = (const float*)d_in[13];
    const float* dec_Wih   = (const float*)d_in[14];
    const float* dec_Whh   = (const float*)d_in[15];
    const float* dec_bih   = (const float*)d_in[16];
    const float* dec_bhh   = (const float*)d_in[17];
    const float* dec_Wfc   = (const float*)d_in[18];
    const float* dec_bfc   = (const float*)d_in[19];
    const int*   source    = (const int*)d_in[20];
    const int*   target    = (const int*)d_in[21];
    float* out = (float*)d_out;

    float* p_emb_s   = symaddr(g_emb_s);
    float* p_gi_f    = symaddr(g_gi_f);
    float* p_gi_b    = symaddr(g_gi_b);
    float* p_h       = symaddr(g_h);
    float* p_enc     = symaddr(g_enc);
    float* p_hfb     = symaddr(g_hfb);
    float* p_state   = symaddr(g_state);
    float* p_encproj = symaddr(g_encproj);
    float* p_feat    = symaddr(g_feat);

    // init h = 0 (both dirs, both parities)
    k_zero<<<(2*2*BB*UU + 255)/256, 256>>>(p_h, 2*2*BB*UU);

    // gather source embeddings
    k_gather_src<<<(SS*BB*EE + 255)/256, 256>>>(emb_src, source);

    // gi_f / gi_b : (2048 x 300) @ (300 x 1536)^T + bih
    {
        dim3 grid(GG/64, (SS*BB)/64);
        k_gemm<<<grid, 256>>>(p_emb_s, EE, enc_Wih_f, EE, 0, enc_bih_f,
                              p_gi_f, GG, SS*BB, GG, EE, 0);
        k_gemm<<<grid, 256>>>(p_emb_s, EE, enc_Wih_b, EE, 0, enc_bih_b,
                              p_gi_b, GG, SS*BB, GG, EE, 0);
    }

    // encoder recurrence: 64 steps, both directions per step
    for (int i = 0; i < SS; i++) {
        int par = i & 1;
        dim3 grid(GG/64, 4, 2);
        k_enc_gh<<<grid, 256>>>(enc_Whh_f, enc_Whh_b, par);
        k_enc_gate<<<(2*BB*UU)/256, 256>>>(i, SS-1-i, par, enc_bhh_f, enc_bhh_b);
    }

    // assemble enc_bt and [hf, hb]
    k_concat_enc<<<(BB*SS*H2 + 255)/256, 256>>>();
    k_concat_hfb<<<(BB*H2 + 255)/256, 256>>>();

    // decoder init state = tanh([hf,hb] @ enc_Wfc^T + enc_bfc)
    {
        dim3 grid(UU/64, 1);
        k_gemm<<<grid, 256>>>(p_hfb, H2, enc_Wfc, H2, 0, enc_bfc,
                              p_state, UU, BB, UU, H2, 1);
    }

    // enc_proj = enc_bt @ attn_W[:, U:3U]^T + attn_b   (rows ordered (b,s))
    {
        dim3 grid(AD/64, (BB*SS)/64);
        k_gemm<<<grid, 256>>>(p_enc, H2, attn_W, GG, UU, attn_b,
                              p_encproj, AD, BB*SS, AD, H2, 0);
    }

    // gather target embeddings for steps 0..T-2
    k_gather_trg<<<(TM1*BB*EE + 255)/256, 256>>>(emb_trg, target);

    // decoder recurrence
    for (int t = 0; t < TM1; t++) {
        int spar = t & 1;
        k_dec_attn<<<BB, 256>>>(spar, attn_W);
        dim3 grid(GG/64, 4, 2);
        k_dec_gemm<<<grid, 256>>>(spar, t, dec_Wih, dec_Whh);
        k_dec_gate<<<(BB*FF + 255)/256, 256>>>(spar, t, dec_bih, dec_bhh);
    }

    // output row 0 = zeros
    k_zero<<<(BB*VTT + 255)/256, 256>>>(out, BB*VTT);

    // logits: (992 x 1836) @ (1836 x 30000)^T + dec_bfc -> out rows 1..31
    {
        dim3 grid((VTT + 63)/64, (TM1*BB + 63)/64);
        k_gemm<<<grid, 256>>>(p_feat, FF, dec_Wfc, FF, 0, dec_bfc,
                              out + (long)BB*VTT, VTT, TM1*BB, VTT, FF, 0);
    }
}

// round 2
// speedup vs baseline: 1.2187x; 1.2187x over previous
#include <cuda_runtime.h>
#include <math.h>

#define SS 64      // source length
#define BB 32      // batch
#define UU 512     // hidden
#define GG 1536    // 3*U
#define EE 300     // embed dim
#define AD 512     // attention dim
#define VTT 30000  // target vocab
#define TT 32      // target length
#define TM1 31     // T-1 decode steps
#define FF 1836    // 3U + E  (logits feature dim)
#define KX 1324    // 2U + E  (decoder GRU input dim)
#define H2 1024    // 2U

// ---------------- device scratch (static, no allocation) ----------------
__device__ float g_emb_s[SS*BB*EE];
__device__ float g_gi_f[SS*BB*GG];
__device__ float g_gi_b[SS*BB*GG];
__device__ float g_outs_f[SS*BB*UU];
__device__ float g_outs_b[SS*BB*UU];
__device__ float g_h[2][2][BB*UU];          // [dir][parity]
__device__ float g_ghp[2][4][BB*GG];        // encoder gh split-K partials
__device__ float g_enc[BB*SS*H2];           // enc_bt (b,s,2U)
__device__ float g_hfb[BB*H2];
__device__ float g_state[2][BB*UU];         // decoder state ping-pong
__device__ float g_encproj[BB*SS*AD];
__device__ float g_embt[TM1*BB*EE];
__device__ float g_ctx[BB*H2];
__device__ float g_dgp[2][4][BB*GG];        // decoder gi/gh split-K partials
__device__ float g_feat[(long)TM1*BB*FF];

__device__ __forceinline__ float sigm(float x) { return 1.0f / (1.0f + expf(-x)); }

// ---- packed f32x2 helpers (FFMA2 only reachable via PTX) ----
__device__ __forceinline__ unsigned long long pk2(float x, float y) {
    unsigned long long r;
    asm("mov.b64 %0, {%1, %2};" : "=l"(r) : "f"(x), "f"(y));
    return r;
}
__device__ __forceinline__ void fma2(unsigned long long& d, unsigned long long a, unsigned long long b) {
    asm("fma.rn.f32x2 %0, %1, %2, %0;" : "+l"(d) : "l"(a), "l"(b));
}
__device__ __forceinline__ float2 upk2(unsigned long long v) {
    float2 f;
    asm("mov.b64 {%0, %1}, %2;" : "=f"(f.x), "=f"(f.y) : "l"(v));
    return f;
}

// ---------------- tiny utility kernels ----------------
__global__ void k_zero(float* p, int n) {
    int i = blockIdx.x * blockDim.x + threadIdx.x;
    if (i < n) p[i] = 0.0f;
}

__global__ void k_gather_src(const float* __restrict__ emb, const int* __restrict__ src) {
    int idx = blockIdx.x * blockDim.x + threadIdx.x;
    if (idx >= SS*BB*EE) return;
    int e = idx % EE; int tb = idx / EE;
    g_emb_s[idx] = emb[(long)src[tb]*EE + e];
}

__global__ void k_gather_trg(const float* __restrict__ emb, const int* __restrict__ trg) {
    int idx = blockIdx.x * blockDim.x + threadIdx.x;
    if (idx >= TM1*BB*EE) return;
    int e = idx % EE; int tb = idx / EE;
    g_embt[idx] = emb[(long)trg[tb]*EE + e];
}

// ---------------- fp32x2 tiled GEMM: C = act(A @ W^T + bias) ----------------
// A: [M, lda] (cols 0..K-1), W: [N, ldw] (cols woff..woff+K-1), K % 4 == 0.
// tile 128x128x16, 256 threads, 8x8 microtile via fma.rn.f32x2.
__global__ void __launch_bounds__(256, 2)
k_gemm(const float* __restrict__ Ap, int lda,
       const float* __restrict__ Wp, int ldw, int woff,
       const float* __restrict__ bias,
       float* __restrict__ Cp, int ldc,
       int M, int N, int K, int act)
{
    __shared__ float sA[16][128];
    __shared__ float sW[16][128];
    int tid = threadIdx.x;
    int m0 = blockIdx.y * 128, n0 = blockIdx.x * 128;
    int tr = tid & 15, tc = tid >> 4;

    unsigned long long acc[8][4];
    #pragma unroll
    for (int i = 0; i < 8; i++)
        #pragma unroll
        for (int j = 0; j < 4; j++) acc[i][j] = 0ull;

    int r  = tid >> 2;          // 0..63
    int kq = (tid & 3) * 4;     // 0,4,8,12

    for (int k0 = 0; k0 < K; k0 += 16) {
        bool kok = (k0 + kq) < K;   // K%4==0 -> whole float4 valid or not
        #pragma unroll
        for (int h = 0; h < 2; h++) {
            int row = r + h * 64;
            float4 va = make_float4(0.f, 0.f, 0.f, 0.f);
            int m = m0 + row;
            if (kok && m < M) va = *reinterpret_cast<const float4*>(&Ap[(long)m*lda + k0 + kq]);
            sA[kq+0][row] = va.x; sA[kq+1][row] = va.y;
            sA[kq+2][row] = va.z; sA[kq+3][row] = va.w;

            float4 vw = make_float4(0.f, 0.f, 0.f, 0.f);
            int n = n0 + row;
            if (kok && n < N) vw = *reinterpret_cast<const float4*>(&Wp[(long)n*ldw + woff + k0 + kq]);
            sW[kq+0][row] = vw.x; sW[kq+1][row] = vw.y;
            sW[kq+2][row] = vw.z; sW[kq+3][row] = vw.w;
        }
        __syncthreads();

        #pragma unroll
        for (int kk = 0; kk < 16; kk++) {
            float4 a0 = *reinterpret_cast<const float4*>(&sA[kk][tr*8]);
            float4 a1 = *reinterpret_cast<const float4*>(&sA[kk][tr*8 + 4]);
            unsigned long long bp[4];
            #pragma unroll
            for (int j = 0; j < 4; j++)
                bp[j] = *reinterpret_cast<const unsigned long long*>(&sW[kk][tc*8 + 2*j]);
            float av[8] = {a0.x, a0.y, a0.z, a0.w, a1.x, a1.y, a1.z, a1.w};
            #pragma unroll
            for (int i = 0; i < 8; i++) {
                unsigned long long ap = pk2(av[i], av[i]);
                #pragma unroll
                for (int j = 0; j < 4; j++) fma2(acc[i][j], ap, bp[j]);
            }
        }
        __syncthreads();
    }

    #pragma unroll
    for (int i = 0; i < 8; i++) {
        int m = m0 + tr*8 + i;
        if (m >= M) continue;
        #pragma unroll
        for (int j = 0; j < 4; j++) {
            float2 v = upk2(acc[i][j]);
            int n = n0 + tc*8 + 2*j;
            if (n < N) {
                float c = v.x + (bias ? bias[n] : 0.0f);
                if (act) c = tanhf(c);
                Cp[(long)m*ldc + n] = c;
            }
            if (n + 1 < N) {
                float c = v.y + (bias ? bias[n+1] : 0.0f);
                if (act) c = tanhf(c);
                Cp[(long)m*ldc + n + 1] = c;
            }
        }
    }
}

// ---------------- encoder recurrent step: gh partials (split-K) ----------------
__global__ void k_enc_gh(const float* __restrict__ Whh_f, const float* __restrict__ Whh_b, int par)
{
    __shared__ float sA[16][32];
    __shared__ float sW[16][64];
    int dir = blockIdx.z, kc = blockIdx.y;
    int n0 = blockIdx.x * 64;
    const float* W = dir ? Whh_b : Whh_f;
    const float* h = g_h[dir][par];
    int tid = threadIdx.x;
    int tm = tid & 15, tn = tid >> 4;
    float acc[2][4] = {};
    int kbase = kc * 128;

    for (int k0 = 0; k0 < 128; k0 += 16) {
        if (tid < 128) {
            int r = tid >> 2, kq = (tid & 3) * 4;
            #pragma unroll
            for (int j = 0; j < 4; j++)
                sA[kq+j][r] = h[r*UU + kbase + k0 + kq + j];
        }
        {
            int r = tid >> 2, kq = (tid & 3) * 4;
            #pragma unroll
            for (int j = 0; j < 4; j++)
                sW[kq+j][r] = W[(long)(n0+r)*UU + kbase + k0 + kq + j];
        }
        __syncthreads();
        #pragma unroll
        for (int kk = 0; kk < 16; kk++) {
            float2 a2 = *reinterpret_cast<const float2*>(&sA[kk][tm*2]);
            float4 b4 = *reinterpret_cast<const float4*>(&sW[kk][tn*4]);
            acc[0][0] = fmaf(a2.x, b4.x, acc[0][0]);
            acc[0][1] = fmaf(a2.x, b4.y, acc[0][1]);
            acc[0][2] = fmaf(a2.x, b4.z, acc[0][2]);
            acc[0][3] = fmaf(a2.x, b4.w, acc[0][3]);
            acc[1][0] = fmaf(a2.y, b4.x, acc[1][0]);
            acc[1][1] = fmaf(a2.y, b4.y, acc[1][1]);
            acc[1][2] = fmaf(a2.y, b4.z, acc[1][2]);
            acc[1][3] = fmaf(a2.y, b4.w, acc[1][3]);
        }
        __syncthreads();
    }
    float* out = &g_ghp[dir][kc][0];
    #pragma unroll
    for (int i = 0; i < 2; i++) {
        int b = tm*2 + i;
        #pragma unroll
        for (int j = 0; j < 4; j++)
            out[b*GG + n0 + tn*4 + j] = acc[i][j];
    }
}

// fused GRU gate update for both directions; writes h[par^1] and outs
__global__ void k_enc_gate(int tf, int tb, int par,
                           const float* __restrict__ bhh_f, const float* __restrict__ bhh_b)
{
    int idx = blockIdx.x * blockDim.x + threadIdx.x;
    if (idx >= 2*BB*UU) return;
    int u = idx & 511;
    int b = (idx >> 9) & 31;
    int dir = idx >> 14;
    const float* gi = dir ? (g_gi_b + (long)tb*BB*GG) : (g_gi_f + (long)tf*BB*GG);
    const float* bhh = dir ? bhh_b : bhh_f;
    float ghr = bhh[u], ghz = bhh[u+UU], ghn = bhh[u+2*UU];
    #pragma unroll
    for (int kc = 0; kc < 4; kc++) {
        const float* p = &g_ghp[dir][kc][b*GG];
        ghr += p[u]; ghz += p[u+UU]; ghn += p[u+2*UU];
    }
    float ir = gi[b*GG + u], iz = gi[b*GG + u + UU], inn = gi[b*GG + u + 2*UU];
    float r = sigm(ir + ghr);
    float z = sigm(iz + ghz);
    float n = tanhf(inn + r*ghn);
    float hp = g_h[dir][par][b*UU + u];
    float hn_ = (1.0f - z)*n + z*hp;
    g_h[dir][par^1][b*UU + u] = hn_;
    float* outs = dir ? (g_outs_b + (long)tb*BB*UU) : (g_outs_f + (long)tf*BB*UU);
    outs[b*UU + u] = hn_;
}

__global__ void k_concat_enc() {
    int idx = blockIdx.x * blockDim.x + threadIdx.x;
    if (idx >= BB*SS*H2) return;
    int h = idx % H2; int bs = idx / H2;
    int s = bs % SS, b = bs / SS;
    float v = (h < UU) ? g_outs_f[((long)s*BB + b)*UU + h]
                       : g_outs_b[((long)s*BB + b)*UU + h - UU];
    g_enc[idx] = v;
}

__global__ void k_concat_hfb() {
    int idx = blockIdx.x * blockDim.x + threadIdx.x;
    if (idx >= BB*H2) return;
    int h = idx % H2; int b = idx / H2;
    float v = (h < UU) ? g_outs_f[((long)(SS-1)*BB + b)*UU + h]
                       : g_outs_b[(long)b*UU + h - UU];
    g_hfb[idx] = v;
}

// ---------------- decoder attention (fused per batch element) ----------------
__global__ void k_dec_attn(int spar, const float* __restrict__ attn_W)
{
    int b = blockIdx.x;
    int tid = threadIdx.x;
    __shared__ float s_st[UU];
    __shared__ float s_tp[AD];
    __shared__ float s_sc[SS];
    __shared__ float s_red[2];

    const float* st = &g_state[spar][b*UU];
    for (int i = tid; i < UU; i += 256) s_st[i] = st[i];
    __syncthreads();

    for (int a = tid; a < AD; a += 256) {
        const float* w = attn_W + (long)a*GG;
        float acc = 0.0f;
        #pragma unroll 4
        for (int k = 0; k < UU; k += 4) {
            float4 wv = *reinterpret_cast<const float4*>(w + k);
            acc = fmaf(s_st[k],   wv.x, acc);
            acc = fmaf(s_st[k+1], wv.y, acc);
            acc = fmaf(s_st[k+2], wv.z, acc);
            acc = fmaf(s_st[k+3], wv.w, acc);
        }
        s_tp[a] = acc;
    }
    __syncthreads();

    {
        int s = tid >> 2, q = tid & 3;
        const float* ep = g_encproj + ((long)b*SS + s)*AD + q*128;
        const float* tp = s_tp + q*128;
        float partial = 0.0f;
        for (int a = 0; a < 128; a++) partial += tanhf(tp[a] + ep[a]);
        partial += __shfl_down_sync(0xffffffffu, partial, 2);
        partial += __shfl_down_sync(0xffffffffu, partial, 1);
        if (q == 0) s_sc[s] = partial;
    }
    __syncthreads();
    if (tid == 0) {
        float mx = s_sc[0];
        for (int s = 1; s < SS; s++) mx = fmaxf(mx, s_sc[s]);
        s_red[0] = mx;
    }
    __syncthreads();
    if (tid < SS) s_sc[tid] = expf(s_sc[tid] - s_red[0]);
    __syncthreads();
    if (tid == 0) {
        float sm = 0.0f;
        for (int s = 0; s < SS; s++) sm += s_sc[s];
        s_red[1] = 1.0f / sm;
    }
    __syncthreads();
    float inv = s_red[1];
    for (int h = tid; h < H2; h += 256) {
        const float* e = g_enc + (long)b*SS*H2 + h;
        float acc = 0.0f;
        #pragma unroll 8
        for (int s = 0; s < SS; s++) acc = fmaf(s_sc[s], e[(long)s*H2], acc);
        g_ctx[b*H2 + h] = acc * inv;
    }
}

// ---------------- decoder GRU matmuls (split-K): z=0 gi (K=1324), z=1 gh (K=512) ----------------
__global__ void k_dec_gemm(int spar, int t,
                           const float* __restrict__ Wih, const float* __restrict__ Whh)
{
    __shared__ float sA[16][32];
    __shared__ float sW[16][64];
    int z = blockIdx.z, kc = blockIdx.y;
    int n0 = blockIdx.x * 64;
    int tid = threadIdx.x;
    int tm = tid & 15, tn = tid >> 4;
    float acc[2][4] = {};
    int K = z ? UU : KX;
    const float* W = z ? Whh : Wih;
    int kchunk = z ? 128 : 332;
    int kbeg = kc * kchunk;
    int kend = min(K, kbeg + kchunk);
    const float* st = g_state[spar];
    const float* em = g_embt + (long)t*BB*EE;

    for (int k0 = kbeg; k0 < kend; k0 += 16) {
        if (tid < 128) {
            int r = tid >> 2, kq = (tid & 3) * 4;
            #pragma unroll
            for (int j = 0; j < 4; j++) {
                int k = k0 + kq + j;
                float v = 0.0f;
                if (k < kend) {
                    if (z) v = st[r*UU + k];
                    else   v = (k < EE) ? em[r*EE + k] : g_ctx[r*H2 + k - EE];
                }
                sA[kq+j][r] = v;
            }
        }
        {
            int r = tid >> 2, kq = (tid & 3) * 4;
            #pragma unroll
            for (int j = 0; j < 4; j++) {
                int k = k0 + kq + j;
                sW[kq+j][r] = (k < kend) ? W[(long)(n0+r)*K + k] : 0.0f;
            }
        }
        __syncthreads();
        #pragma unroll
        for (int kk = 0; kk < 16; kk++) {
            float2 a2 = *reinterpret_cast<const float2*>(&sA[kk][tm*2]);
            float4 b4 = *reinterpret_cast<const float4*>(&sW[kk][tn*4]);
            acc[0][0] = fmaf(a2.x, b4.x, acc[0][0]);
            acc[0][1] = fmaf(a2.x, b4.y, acc[0][1]);
            acc[0][2] = fmaf(a2.x, b4.z, acc[0][2]);
            acc[0][3] = fmaf(a2.x, b4.w, acc[0][3]);
            acc[1][0] = fmaf(a2.y, b4.x, acc[1][0]);
            acc[1][1] = fmaf(a2.y, b4.y, acc[1][1]);
            acc[1][2] = fmaf(a2.y, b4.z, acc[1][2]);
            acc[1][3] = fmaf(a2.y, b4.w, acc[1][3]);
        }
        __syncthreads();
    }
    float* out = &g_dgp[z][kc][0];
    #pragma unroll
    for (int i = 0; i < 2; i++) {
        int b = tm*2 + i;
        #pragma unroll
        for (int j = 0; j < 4; j++)
            out[b*GG + n0 + tn*4 + j] = acc[i][j];
    }
}

// decoder gate + feature row assembly [st2, ctx, emb_t]
__global__ void k_dec_gate(int spar, int t,
                           const float* __restrict__ bih, const float* __restrict__ bhh)
{
    int idx = blockIdx.x * blockDim.x + threadIdx.x;
    if (idx >= BB*FF) return;
    int f = idx % FF; int b = idx / FF;
    float* feat = g_feat + ((long)t*BB + b)*FF;
    if (f < UU) {
        int u = f;
        float gir = bih[u], giz = bih[u+UU], gin = bih[u+2*UU];
        float ghr = bhh[u], ghz = bhh[u+UU], ghn = bhh[u+2*UU];
        #pragma unroll
        for (int kc = 0; kc < 4; kc++) {
            const float* pi = &g_dgp[0][kc][b*GG];
            const float* ph = &g_dgp[1][kc][b*GG];
            gir += pi[u]; giz += pi[u+UU]; gin += pi[u+2*UU];
            ghr += ph[u]; ghz += ph[u+UU]; ghn += ph[u+2*UU];
        }
        float r = sigm(gir + ghr);
        float z = sigm(giz + ghz);
        float n = tanhf(gin + r*ghn);
        float hp = g_state[spar][b*UU + u];
        float h2 = (1.0f - z)*n + z*hp;
        g_state[spar^1][b*UU + u] = h2;
        feat[u] = h2;
    } else if (f < UU + H2) {
        feat[f] = g_ctx[b*H2 + f - UU];
    } else {
        feat[f] = g_embt[((long)t*BB + b)*EE + f - UU - H2];
    }
}

// ---------------- host launch ----------------
static float* symaddr(const void* sym) {
    void* p = nullptr;
    cudaGetSymbolAddress(&p, sym);
    return (float*)p;
}

extern "C" void kernel_launch(void* const* d_in, const int* in_sizes, int n_in,
                              void* d_out, int out_size)
{
    const float* emb_src   = (const float*)d_in[0];
    const float* emb_trg   = (const float*)d_in[1];
    const float* enc_Wih_f = (const float*)d_in[2];
    const float* enc_Whh_f = (const float*)d_in[3];
    const float* enc_bih_f = (const float*)d_in[4];
    const float* enc_bhh_f = (const float*)d_in[5];
    const float* enc_Wih_b = (const float*)d_in[6];
    const float* enc_Whh_b = (const float*)d_in[7];
    const float* enc_bih_b = (const float*)d_in[8];
    const float* enc_bhh_b = (const float*)d_in[9];
    const float* enc_Wfc   = (const float*)d_in[10];
    const float* enc_bfc   = (const float*)d_in[11];
    const float* attn_W    = (const float*)d_in[12];
    const float* attn_b    = (const float*)d_in[13];
    const float* dec_Wih   = (const float*)d_in[14];
    const float* dec_Whh   = (const float*)d_in[15];
    const float* dec_bih   = (const float*)d_in[16];
    const float* dec_bhh   = (const float*)d_in[17];
    const float* dec_Wfc   = (const float*)d_in[18];
    const float* dec_bfc   = (const float*)d_in[19];
    const int*   source    = (const int*)d_in[20];
    const int*   target    = (const int*)d_in[21];
    float* out = (float*)d_out;

    float* p_emb_s   = symaddr(g_emb_s);
    float* p_gi_f    = symaddr(g_gi_f);
    float* p_gi_b    = symaddr(g_gi_b);
    float* p_h       = symaddr(g_h);
    float* p_enc     = symaddr(g_enc);
    float* p_hfb     = symaddr(g_hfb);
    float* p_state   = symaddr(g_state);
    float* p_encproj = symaddr(g_encproj);
    float* p_feat    = symaddr(g_feat);

    // init h = 0 (both dirs, both parities)
    k_zero<<<(2*2*BB*UU + 255)/256, 256>>>(p_h, 2*2*BB*UU);

    // gather source embeddings
    k_gather_src<<<(SS*BB*EE + 255)/256, 256>>>(emb_src, source);

    // gi_f / gi_b : (2048 x 300) @ (300 x 1536)^T + bih
    {
        dim3 grid(GG/128, (SS*BB)/128);
        k_gemm<<<grid, 256>>>(p_emb_s, EE, enc_Wih_f, EE, 0, enc_bih_f,
                              p_gi_f, GG, SS*BB, GG, EE, 0);
        k_gemm<<<grid, 256>>>(p_emb_s, EE, enc_Wih_b, EE, 0, enc_bih_b,
                              p_gi_b, GG, SS*BB, GG, EE, 0);
    }

    // encoder recurrence: 64 steps, both directions per step
    for (int i = 0; i < SS; i++) {
        int par = i & 1;
        dim3 grid(GG/64, 4, 2);
        k_enc_gh<<<grid, 256>>>(enc_Whh_f, enc_Whh_b, par);
        k_enc_gate<<<(2*BB*UU)/256, 256>>>(i, SS-1-i, par, enc_bhh_f, enc_bhh_b);
    }

    // assemble enc_bt and [hf, hb]
    k_concat_enc<<<(BB*SS*H2 + 255)/256, 256>>>();
    k_concat_hfb<<<(BB*H2 + 255)/256, 256>>>();

    // decoder init state = tanh([hf,hb] @ enc_Wfc^T + enc_bfc)
    {
        dim3 grid((UU + 127)/128, 1);
        k_gemm<<<grid, 256>>>(p_hfb, H2, enc_Wfc, H2, 0, enc_bfc,
                              p_state, UU, BB, UU, H2, 1);
    }

    // enc_proj = enc_bt @ attn_W[:, U:3U]^T + attn_b   (rows ordered (b,s))
    {
        dim3 grid(AD/128, (BB*SS)/128);
        k_gemm<<<grid, 256>>>(p_enc, H2, attn_W, GG, UU, attn_b,
                              p_encproj, AD, BB*SS, AD, H2, 0);
    }

    // gather target embeddings for steps 0..T-2
    k_gather_trg<<<(TM1*BB*EE + 255)/256, 256>>>(emb_trg, target);

    // decoder recurrence
    for (int t = 0; t < TM1; t++) {
        int spar = t & 1;
        k_dec_attn<<<BB, 256>>>(spar, attn_W);
        dim3 grid(GG/64, 4, 2);
        k_dec_gemm<<<grid, 256>>>(spar, t, dec_Wih, dec_Whh);
        k_dec_gate<<<(BB*FF + 255)/256, 256>>>(spar, t, dec_bih, dec_bhh);
    }

    // output row 0 = zeros
    k_zero<<<(BB*VTT + 255)/256, 256>>>(out, BB*VTT);

    // logits: (992 x 1836) @ (1836 x 30000)^T + dec_bfc -> out rows 1..31
    {
        dim3 grid((VTT + 127)/128, (TM1*BB + 127)/128);
        k_gemm<<<grid, 256>>>(p_feat, FF, dec_Wfc, FF, 0, dec_bfc,
                              out + (long)BB*VTT, VTT, TM1*BB, VTT, FF, 0);
    }
}

// round 4
// speedup vs baseline: 1.6616x; 1.3635x over previous
#include <cuda_runtime.h>
#include <cuda_bf16.h>
#include <math.h>
#include <stdint.h>

#define SS 64      // source length
#define BB 32      // batch
#define UU 512     // hidden
#define GG 1536    // 3*U
#define EE 300     // embed dim
#define AD 512     // attention dim
#define VTT 30000  // target vocab
#define TT 32      // target length
#define TM1 31     // T-1 decode steps
#define FF 1836    // 3U + E  (logits feature dim)
#define KX 1324    // 2U + E  (decoder GRU input dim)
#define H2 1024    // 2U
#define MTOT (TM1*BB)   // 992

// logits GEMM padded dims
#define KP 1856         // 29 * 64
#define NP 30080        // 235 * 128
#define MP 1024         // 8 * 128

// ---------------- device scratch (static, no allocation) ----------------
__device__ float g_emb_s[SS*BB*EE];
__device__ float g_gi_f[SS*BB*GG];
__device__ float g_gi_b[SS*BB*GG];
__device__ float g_outs_f[SS*BB*UU];
__device__ float g_outs_b[SS*BB*UU];
__device__ float g_h[2][2][BB*UU];          // [dir][parity]
__device__ float g_ghp[2][4][BB*GG];        // encoder gh split-K partials
__device__ float g_enc[BB*SS*H2];           // enc_bt (b,s,2U)
__device__ float g_hfb[BB*H2];
__device__ float g_state[2][BB*UU];         // decoder state ping-pong
__device__ float g_encproj[BB*SS*AD];
__device__ float g_embt[TM1*BB*EE];
__device__ float g_ctx[BB*H2];
__device__ float g_dgp[2][4][BB*GG];        // decoder gi/gh split-K partials
__device__ float g_feat[(long)TM1*BB*FF];

// split-bf16 operands for the logits GEMM
__device__ __nv_bfloat16 g_whi[(long)NP*KP];
__device__ __nv_bfloat16 g_wlo[(long)NP*KP];
__device__ __nv_bfloat16 g_ahi[(long)MP*KP];
__device__ __nv_bfloat16 g_alo[(long)MP*KP];

__device__ __forceinline__ float sigm(float x) { return 1.0f / (1.0f + expf(-x)); }

// ---- packed f32x2 helpers (FFMA2 only reachable via PTX) ----
__device__ __forceinline__ unsigned long long pk2(float x, float y) {
    unsigned long long r;
    asm("mov.b64 %0, {%1, %2};" : "=l"(r) : "f"(x), "f"(y));
    return r;
}
__device__ __forceinline__ void fma2(unsigned long long& d, unsigned long long a, unsigned long long b) {
    asm("fma.rn.f32x2 %0, %1, %2, %0;" : "+l"(d) : "l"(a), "l"(b));
}
__device__ __forceinline__ float2 upk2(unsigned long long v) {
    float2 f;
    asm("mov.b64 {%0, %1}, %2;" : "=f"(f.x), "=f"(f.y) : "l"(v));
    return f;
}

// ---------------- tiny utility kernels ----------------
__global__ void k_zero(float* p, int n) {
    int i = blockIdx.x * blockDim.x + threadIdx.x;
    if (i < n) p[i] = 0.0f;
}

__global__ void k_gather_src(const float* __restrict__ emb, const int* __restrict__ src) {
    int idx = blockIdx.x * blockDim.x + threadIdx.x;
    if (idx >= SS*BB*EE) return;
    int e = idx % EE; int tb = idx / EE;
    g_emb_s[idx] = emb[(long)src[tb]*EE + e];
}

__global__ void k_gather_trg(const float* __restrict__ emb, const int* __restrict__ trg) {
    int idx = blockIdx.x * blockDim.x + threadIdx.x;
    if (idx >= TM1*BB*EE) return;
    int e = idx % EE; int tb = idx / EE;
    g_embt[idx] = emb[(long)trg[tb]*EE + e];
}

// ---------------- split kernels: fp32 -> bf16 hi/lo ----------------
__global__ void k_split_w(const float* __restrict__ W) {
    int idx = blockIdx.x * blockDim.x + threadIdx.x;
    if (idx >= NP*KP) return;
    int k = idx % KP; int n = idx / KP;
    float x = (n < VTT && k < FF) ? W[(long)n*FF + k] : 0.0f;
    __nv_bfloat16 h = __float2bfloat16(x);
    g_whi[idx] = h;
    g_wlo[idx] = __float2bfloat16(x - __bfloat162float(h));
}

__global__ void k_split_a() {
    int idx = blockIdx.x * blockDim.x + threadIdx.x;
    if (idx >= MP*KP) return;
    int k = idx % KP; int m = idx / KP;
    float x = (m < MTOT && k < FF) ? g_feat[(long)m*FF + k] : 0.0f;
    __nv_bfloat16 h = __float2bfloat16(x);
    g_ahi[idx] = h;
    g_alo[idx] = __float2bfloat16(x - __bfloat162float(h));
}

// ---------------- fp32x2 tiled GEMM: C = act(A @ W^T + bias) ----------------
__global__ void __launch_bounds__(256, 2)
k_gemm(const float* __restrict__ Ap, int lda,
       const float* __restrict__ Wp, int ldw, int woff,
       const float* __restrict__ bias,
       float* __restrict__ Cp, int ldc,
       int M, int N, int K, int act)
{
    __shared__ float sA[16][128];
    __shared__ float sW[16][128];
    int tid = threadIdx.x;
    int m0 = blockIdx.y * 128, n0 = blockIdx.x * 128;
    int tr = tid & 15, tc = tid >> 4;

    unsigned long long acc[8][4];
    #pragma unroll
    for (int i = 0; i < 8; i++)
        #pragma unroll
        for (int j = 0; j < 4; j++) acc[i][j] = 0ull;

    int r  = tid >> 2;
    int kq = (tid & 3) * 4;

    for (int k0 = 0; k0 < K; k0 += 16) {
        bool kok = (k0 + kq) < K;
        #pragma unroll
        for (int h = 0; h < 2; h++) {
            int row = r + h * 64;
            float4 va = make_float4(0.f, 0.f, 0.f, 0.f);
            int m = m0 + row;
            if (kok && m < M) va = *reinterpret_cast<const float4*>(&Ap[(long)m*lda + k0 + kq]);
            sA[kq+0][row] = va.x; sA[kq+1][row] = va.y;
            sA[kq+2][row] = va.z; sA[kq+3][row] = va.w;

            float4 vw = make_float4(0.f, 0.f, 0.f, 0.f);
            int n = n0 + row;
            if (kok && n < N) vw = *reinterpret_cast<const float4*>(&Wp[(long)n*ldw + woff + k0 + kq]);
            sW[kq+0][row] = vw.x; sW[kq+1][row] = vw.y;
            sW[kq+2][row] = vw.z; sW[kq+3][row] = vw.w;
        }
        __syncthreads();

        #pragma unroll
        for (int kk = 0; kk < 16; kk++) {
            float4 a0 = *reinterpret_cast<const float4*>(&sA[kk][tr*8]);
            float4 a1 = *reinterpret_cast<const float4*>(&sA[kk][tr*8 + 4]);
            unsigned long long bp[4];
            #pragma unroll
            for (int j = 0; j < 4; j++)
                bp[j] = *reinterpret_cast<const unsigned long long*>(&sW[kk][tc*8 + 2*j]);
            float av[8] = {a0.x, a0.y, a0.z, a0.w, a1.x, a1.y, a1.z, a1.w};
            #pragma unroll
            for (int i = 0; i < 8; i++) {
                unsigned long long ap = pk2(av[i], av[i]);
                #pragma unroll
                for (int j = 0; j < 4; j++) fma2(acc[i][j], ap, bp[j]);
            }
        }
        __syncthreads();
    }

    #pragma unroll
    for (int i = 0; i < 8; i++) {
        int m = m0 + tr*8 + i;
        if (m >= M) continue;
        #pragma unroll
        for (int j = 0; j < 4; j++) {
            float2 v = upk2(acc[i][j]);
            int n = n0 + tc*8 + 2*j;
            if (n < N) {
                float c = v.x + (bias ? bias[n] : 0.0f);
                if (act) c = tanhf(c);
                Cp[(long)m*ldc + n] = c;
            }
            if (n + 1 < N) {
                float c = v.y + (bias ? bias[n+1] : 0.0f);
                if (act) c = tanhf(c);
                Cp[(long)m*ldc + n + 1] = c;
            }
        }
    }
}

// ================= mma.sync bf16 logits GEMM =================
__device__ __forceinline__ uint32_t smem_u32(const void* p) {
    uint32_t a;
    asm("{ .reg .u64 t; cvta.to.shared.u64 t, %1; cvt.u32.u64 %0, t; }" : "=r"(a) : "l"(p));
    return a;
}
__device__ __forceinline__ void cpa16(uint32_t dst, const void* src) {
    asm volatile("cp.async.cg.shared.global [%0], [%1], 16;" :: "r"(dst), "l"(src) : "memory");
}
__device__ __forceinline__ void cpa_commit() {
    asm volatile("cp.async.commit_group;" ::: "memory");
}
__device__ __forceinline__ void ldsm4(uint32_t* r, uint32_t addr) {
    asm volatile("ldmatrix.sync.aligned.m8n8.x4.shared.b16 {%0,%1,%2,%3}, [%4];"
        : "=r"(r[0]), "=r"(r[1]), "=r"(r[2]), "=r"(r[3]) : "r"(addr));
}
__device__ __forceinline__ void mma16816(float* d, const uint32_t* a, const uint32_t* b) {
    asm volatile("mma.sync.aligned.m16n8k16.row.col.f32.bf16.bf16.f32 "
        "{%0,%1,%2,%3}, {%4,%5,%6,%7}, {%8,%9}, {%0,%1,%2,%3};"
        : "+f"(d[0]), "+f"(d[1]), "+f"(d[2]), "+f"(d[3])
        : "r"(a[0]), "r"(a[1]), "r"(a[2]), "r"(a[3]), "r"(b[0]), "r"(b[1]));
}

// CTA tile 128(M) x 128(N), K staged 64 deep, 2 stages, 8 warps (2M x 4N).
// smem per stage: Ahi 16K | Alo 16K | Bhi 16K | Blo 16K = 64KB; 2 stages = 128KB.
#define LSTG 65536
#define LOG_SMEM (2*LSTG)

__global__ void __launch_bounds__(256, 1)
k_logits_mma(const float* __restrict__ bias, float* __restrict__ outp)
{
    extern __shared__ __align__(128) char smem[];
    uint32_t sb = smem_u32(smem);
    int tid = threadIdx.x;
    int wid = tid >> 5, lane = tid & 31;
    int wm = wid >> 2, wn = wid & 3;       // warp 64x32 tile
    int grp = lane >> 3, lr = lane & 7;
    int m0 = blockIdx.x * 128;
    int n0 = blockIdx.y * 128;

    const __nv_bfloat16* ahi = g_ahi;
    const __nv_bfloat16* alo = g_alo;
    const __nv_bfloat16* whi = g_whi;
    const __nv_bfloat16* wlo = g_wlo;

    float acc[4][4][4];
    #pragma unroll
    for (int i = 0; i < 4; i++)
        #pragma unroll
        for (int j = 0; j < 4; j++)
            #pragma unroll
            for (int c = 0; c < 4; c++) acc[i][j][c] = 0.0f;

    // stage loader: 16 cp.async per thread
    auto load_stage = [&](int it, int s) {
        int k0 = it * 64;
        uint32_t base = sb + s * LSTG;
        #pragma unroll
        for (int q = 0; q < 4; q++) {
            int u = tid + q * 256;
            int row = u >> 3, c = u & 7;
            uint32_t off = row * 128 + (((uint32_t)(c ^ (row & 7))) << 4);
            long ga = (long)(m0 + row) * KP + k0 + c * 8;
            cpa16(base + off,          ahi + ga);
            cpa16(base + 16384 + off,  alo + ga);
            long gb = (long)(n0 + row) * KP + k0 + c * 8;
            cpa16(base + 32768 + off,  whi + gb);
            cpa16(base + 49152 + off,  wlo + gb);
        }
    };

    load_stage(0, 0);
    cpa_commit();

    for (int it = 0; it < 29; it++) {
        int s = it & 1;
        if (it < 28) {
            load_stage(it + 1, s ^ 1);
            cpa_commit();
            asm volatile("cp.async.wait_group 1;" ::: "memory");
        } else {
            asm volatile("cp.async.wait_group 0;" ::: "memory");
        }
        __syncthreads();

        uint32_t aAhi = sb + s*LSTG;
        uint32_t aAlo = aAhi + 16384;
        uint32_t aBhi = aAhi + 32768;
        uint32_t aBlo = aAhi + 49152;

        #pragma unroll
        for (int ks = 0; ks < 4; ks++) {
            uint32_t fa_hi[4][4], fa_lo[4][4];
            #pragma unroll
            for (int mt = 0; mt < 4; mt++) {
                int row = wm*64 + mt*16 + lr + (grp & 1) * 8;
                int c = 2*ks + (grp >> 1);
                uint32_t off = row * 128 + (((uint32_t)(c ^ (row & 7))) << 4);
                ldsm4(fa_hi[mt], aAhi + off);
                ldsm4(fa_lo[mt], aAlo + off);
            }
            uint32_t fb_hi[2][4], fb_lo[2][4];
            #pragma unroll
            for (int p = 0; p < 2; p++) {
                int nrow = wn*32 + p*16 + lr + (grp >> 1) * 8;
                int c = 2*ks + (grp & 1);
                uint32_t off = nrow * 128 + (((uint32_t)(c ^ (nrow & 7))) << 4);
                ldsm4(fb_hi[p], aBhi + off);
                ldsm4(fb_lo[p], aBlo + off);
            }
            #pragma unroll
            for (int mt = 0; mt < 4; mt++) {
                #pragma unroll
                for (int nt = 0; nt < 4; nt++) {
                    const uint32_t* bh = &fb_hi[nt >> 1][(nt & 1) * 2];
                    const uint32_t* bl = &fb_lo[nt >> 1][(nt & 1) * 2];
                    mma16816(acc[mt][nt], fa_hi[mt], bh);
                    mma16816(acc[mt][nt], fa_lo[mt], bh);
                    mma16816(acc[mt][nt], fa_hi[mt], bl);
                }
            }
        }
        __syncthreads();
    }

    // epilogue: D[m][n] + bias[n]
    int mrow = (lane >> 2);
    int ncol = (lane & 3) * 2;
    #pragma unroll
    for (int mt = 0; mt < 4; mt++) {
        #pragma unroll
        for (int nt = 0; nt < 4; nt++) {
            int n = n0 + wn*32 + nt*8 + ncol;
            if (n >= VTT) continue;
            float2 bv = *reinterpret_cast<const float2*>(&bias[n]);
            int m1 = m0 + wm*64 + mt*16 + mrow;
            int m2 = m1 + 8;
            if (m1 < MTOT) {
                float2 v = make_float2(acc[mt][nt][0] + bv.x, acc[mt][nt][1] + bv.y);
                *reinterpret_cast<float2*>(&outp[(long)m1*VTT + n]) = v;
            }
            if (m2 < MTOT) {
                float2 v = make_float2(acc[mt][nt][2] + bv.x, acc[mt][nt][3] + bv.y);
                *reinterpret_cast<float2*>(&outp[(long)m2*VTT + n]) = v;
            }
        }
    }
}

// ---------------- encoder recurrent step: gh partials (split-K) ----------------
__global__ void k_enc_gh(const float* __restrict__ Whh_f, const float* __restrict__ Whh_b, int par)
{
    __shared__ float sA[16][32];
    __shared__ float sW[16][64];
    int dir = blockIdx.z, kc = blockIdx.y;
    int n0 = blockIdx.x * 64;
    const float* W = dir ? Whh_b : Whh_f;
    const float* h = g_h[dir][par];
    int tid = threadIdx.x;
    int tm = tid & 15, tn = tid >> 4;
    float acc[2][4] = {};
    int kbase = kc * 128;

    for (int k0 = 0; k0 < 128; k0 += 16) {
        if (tid < 128) {
            int r = tid >> 2, kq = (tid & 3) * 4;
            #pragma unroll
            for (int j = 0; j < 4; j++)
                sA[kq+j][r] = h[r*UU + kbase + k0 + kq + j];
        }
        {
            int r = tid >> 2, kq = (tid & 3) * 4;
            #pragma unroll
            for (int j = 0; j < 4; j++)
                sW[kq+j][r] = W[(long)(n0+r)*UU + kbase + k0 + kq + j];
        }
        __syncthreads();
        #pragma unroll
        for (int kk = 0; kk < 16; kk++) {
            float2 a2 = *reinterpret_cast<const float2*>(&sA[kk][tm*2]);
            float4 b4 = *reinterpret_cast<const float4*>(&sW[kk][tn*4]);
            acc[0][0] = fmaf(a2.x, b4.x, acc[0][0]);
            acc[0][1] = fmaf(a2.x, b4.y, acc[0][1]);
            acc[0][2] = fmaf(a2.x, b4.z, acc[0][2]);
            acc[0][3] = fmaf(a2.x, b4.w, acc[0][3]);
            acc[1][0] = fmaf(a2.y, b4.x, acc[1][0]);
            acc[1][1] = fmaf(a2.y, b4.y, acc[1][1]);
            acc[1][2] = fmaf(a2.y, b4.z, acc[1][2]);
            acc[1][3] = fmaf(a2.y, b4.w, acc[1][3]);
        }
        __syncthreads();
    }
    float* out = &g_ghp[dir][kc][0];
    #pragma unroll
    for (int i = 0; i < 2; i++) {
        int b = tm*2 + i;
        #pragma unroll
        for (int j = 0; j < 4; j++)
            out[b*GG + n0 + tn*4 + j] = acc[i][j];
    }
}

__global__ void k_enc_gate(int tf, int tb, int par,
                           const float* __restrict__ bhh_f, const float* __restrict__ bhh_b)
{
    int idx = blockIdx.x * blockDim.x + threadIdx.x;
    if (idx >= 2*BB*UU) return;
    int u = idx & 511;
    int b = (idx >> 9) & 31;
    int dir = idx >> 14;
    const float* gi = dir ? (g_gi_b + (long)tb*BB*GG) : (g_gi_f + (long)tf*BB*GG);
    const float* bhh = dir ? bhh_b : bhh_f;
    float ghr = bhh[u], ghz = bhh[u+UU], ghn = bhh[u+2*UU];
    #pragma unroll
    for (int kc = 0; kc < 4; kc++) {
        const float* p = &g_ghp[dir][kc][b*GG];
        ghr += p[u]; ghz += p[u+UU]; ghn += p[u+2*UU];
    }
    float ir = gi[b*GG + u], iz = gi[b*GG + u + UU], inn = gi[b*GG + u + 2*UU];
    float r = sigm(ir + ghr);
    float z = sigm(iz + ghz);
    float n = tanhf(inn + r*ghn);
    float hp = g_h[dir][par][b*UU + u];
    float hn_ = (1.0f - z)*n + z*hp;
    g_h[dir][par^1][b*UU + u] = hn_;
    float* outs = dir ? (g_outs_b + (long)tb*BB*UU) : (g_outs_f + (long)tf*BB*UU);
    outs[b*UU + u] = hn_;
}

__global__ void k_concat_enc() {
    int idx = blockIdx.x * blockDim.x + threadIdx.x;
    if (idx >= BB*SS*H2) return;
    int h = idx % H2; int bs = idx / H2;
    int s = bs % SS, b = bs / SS;
    float v = (h < UU) ? g_outs_f[((long)s*BB + b)*UU + h]
                       : g_outs_b[((long)s*BB + b)*UU + h - UU];
    g_enc[idx] = v;
}

__global__ void k_concat_hfb() {
    int idx = blockIdx.x * blockDim.x + threadIdx.x;
    if (idx >= BB*H2) return;
    int h = idx % H2; int b = idx / H2;
    float v = (h < UU) ? g_outs_f[((long)(SS-1)*BB + b)*UU + h]
                       : g_outs_b[(long)b*UU + h - UU];
    g_hfb[idx] = v;
}

// ---------------- decoder attention (fused per batch element) ----------------
__global__ void k_dec_attn(int spar, const float* __restrict__ attn_W)
{
    int b = blockIdx.x;
    int tid = threadIdx.x;
    __shared__ float s_st[UU];
    __shared__ float s_tp[AD];
    __shared__ float s_sc[SS];
    __shared__ float s_red[2];

    const float* st = &g_state[spar][b*UU];
    for (int i = tid; i < UU; i += 256) s_st[i] = st[i];
    __syncthreads();

    for (int a = tid; a < AD; a += 256) {
        const float* w = attn_W + (long)a*GG;
        float acc = 0.0f;
        #pragma unroll 4
        for (int k = 0; k < UU; k += 4) {
            float4 wv = *reinterpret_cast<const float4*>(w + k);
            acc = fmaf(s_st[k],   wv.x, acc);
            acc = fmaf(s_st[k+1], wv.y, acc);
            acc = fmaf(s_st[k+2], wv.z, acc);
            acc = fmaf(s_st[k+3], wv.w, acc);
        }
        s_tp[a] = acc;
    }
    __syncthreads();

    {
        int s = tid >> 2, q = tid & 3;
        const float* ep = g_encproj + ((long)b*SS + s)*AD + q*128;
        const float* tp = s_tp + q*128;
        float partial = 0.0f;
        for (int a = 0; a < 128; a++) partial += tanhf(tp[a] + ep[a]);
        partial += __shfl_down_sync(0xffffffffu, partial, 2);
        partial += __shfl_down_sync(0xffffffffu, partial, 1);
        if (q == 0) s_sc[s] = partial;
    }
    __syncthreads();
    if (tid == 0) {
        float mx = s_sc[0];
        for (int s = 1; s < SS; s++) mx = fmaxf(mx, s_sc[s]);
        s_red[0] = mx;
    }
    __syncthreads();
    if (tid < SS) s_sc[tid] = expf(s_sc[tid] - s_red[0]);
    __syncthreads();
    if (tid == 0) {
        float sm = 0.0f;
        for (int s = 0; s < SS; s++) sm += s_sc[s];
        s_red[1] = 1.0f / sm;
    }
    __syncthreads();
    float inv = s_red[1];
    for (int h = tid; h < H2; h += 256) {
        const float* e = g_enc + (long)b*SS*H2 + h;
        float acc = 0.0f;
        #pragma unroll 8
        for (int s = 0; s < SS; s++) acc = fmaf(s_sc[s], e[(long)s*H2], acc);
        g_ctx[b*H2 + h] = acc * inv;
    }
}

// ---------------- decoder GRU matmuls (split-K) ----------------
__global__ void k_dec_gemm(int spar, int t,
                           const float* __restrict__ Wih, const float* __restrict__ Whh)
{
    __shared__ float sA[16][32];
    __shared__ float sW[16][64];
    int z = blockIdx.z, kc = blockIdx.y;
    int n0 = blockIdx.x * 64;
    int tid = threadIdx.x;
    int tm = tid & 15, tn = tid >> 4;
    float acc[2][4] = {};
    int K = z ? UU : KX;
    const float* W = z ? Whh : Wih;
    int kchunk = z ? 128 : 332;
    int kbeg = kc * kchunk;
    int kend = min(K, kbeg + kchunk);
    const float* st = g_state[spar];
    const float* em = g_embt + (long)t*BB*EE;

    for (int k0 = kbeg; k0 < kend; k0 += 16) {
        if (tid < 128) {
            int r = tid >> 2, kq = (tid & 3) * 4;
            #pragma unroll
            for (int j = 0; j < 4; j++) {
                int k = k0 + kq + j;
                float v = 0.0f;
                if (k < kend) {
                    if (z) v = st[r*UU + k];
                    else   v = (k < EE) ? em[r*EE + k] : g_ctx[r*H2 + k - EE];
                }
                sA[kq+j][r] = v;
            }
        }
        {
            int r = tid >> 2, kq = (tid & 3) * 4;
            #pragma unroll
            for (int j = 0; j < 4; j++) {
                int k = k0 + kq + j;
                sW[kq+j][r] = (k < kend) ? W[(long)(n0+r)*K + k] : 0.0f;
            }
        }
        __syncthreads();
        #pragma unroll
        for (int kk = 0; kk < 16; kk++) {
            float2 a2 = *reinterpret_cast<const float2*>(&sA[kk][tm*2]);
            float4 b4 = *reinterpret_cast<const float4*>(&sW[kk][tn*4]);
            acc[0][0] = fmaf(a2.x, b4.x, acc[0][0]);
            acc[0][1] = fmaf(a2.x, b4.y, acc[0][1]);
            acc[0][2] = fmaf(a2.x, b4.z, acc[0][2]);
            acc[0][3] = fmaf(a2.x, b4.w, acc[0][3]);
            acc[1][0] = fmaf(a2.y, b4.x, acc[1][0]);
            acc[1][1] = fmaf(a2.y, b4.y, acc[1][1]);
            acc[1][2] = fmaf(a2.y, b4.z, acc[1][2]);
            acc[1][3] = fmaf(a2.y, b4.w, acc[1][3]);
        }
        __syncthreads();
    }
    float* out = &g_dgp[z][kc][0];
    #pragma unroll
    for (int i = 0; i < 2; i++) {
        int b = tm*2 + i;
        #pragma unroll
        for (int j = 0; j < 4; j++)
            out[b*GG + n0 + tn*4 + j] = acc[i][j];
    }
}

__global__ void k_dec_gate(int spar, int t,
                           const float* __restrict__ bih, const float* __restrict__ bhh)
{
    int idx = blockIdx.x * blockDim.x + threadIdx.x;
    if (idx >= BB*FF) return;
    int f = idx % FF; int b = idx / FF;
    float* feat = g_feat + ((long)t*BB + b)*FF;
    if (f < UU) {
        int u = f;
        float gir = bih[u], giz = bih[u+UU], gin = bih[u+2*UU];
        float ghr = bhh[u], ghz = bhh[u+UU], ghn = bhh[u+2*UU];
        #pragma unroll
        for (int kc = 0; kc < 4; kc++) {
            const float* pi = &g_dgp[0][kc][b*GG];
            const float* ph = &g_dgp[1][kc][b*GG];
            gir += pi[u]; giz += pi[u+UU]; gin += pi[u+2*UU];
            ghr += ph[u]; ghz += ph[u+UU]; ghn += ph[u+2*UU];
        }
        float r = sigm(gir + ghr);
        float z = sigm(giz + ghz);
        float n = tanhf(gin + r*ghn);
        float hp = g_state[spar][b*UU + u];
        float h2 = (1.0f - z)*n + z*hp;
        g_state[spar^1][b*UU + u] = h2;
        feat[u] = h2;
    } else if (f < UU + H2) {
        feat[f] = g_ctx[b*H2 + f - UU];
    } else {
        feat[f] = g_embt[((long)t*BB + b)*EE + f - UU - H2];
    }
}

// ---------------- host launch ----------------
static float* symaddr(const void* sym) {
    void* p = nullptr;
    cudaGetSymbolAddress(&p, sym);
    return (float*)p;
}

extern "C" void kernel_launch(void* const* d_in, const int* in_sizes, int n_in,
                              void* d_out, int out_size)
{
    const float* emb_src   = (const float*)d_in[0];
    const float* emb_trg   = (const float*)d_in[1];
    const float* enc_Wih_f = (const float*)d_in[2];
    const float* enc_Whh_f = (const float*)d_in[3];
    const float* enc_bih_f = (const float*)d_in[4];
    const float* enc_bhh_f = (const float*)d_in[5];
    const float* enc_Wih_b = (const float*)d_in[6];
    const float* enc_Whh_b = (const float*)d_in[7];
    const float* enc_bih_b = (const float*)d_in[8];
    const float* enc_bhh_b = (const float*)d_in[9];
    const float* enc_Wfc   = (const float*)d_in[10];
    const float* enc_bfc   = (const float*)d_in[11];
    const float* attn_W    = (const float*)d_in[12];
    const float* attn_b    = (const float*)d_in[13];
    const float* dec_Wih   = (const float*)d_in[14];
    const float* dec_Whh   = (const float*)d_in[15];
    const float* dec_bih   = (const float*)d_in[16];
    const float* dec_bhh   = (const float*)d_in[17];
    const float* dec_Wfc   = (const float*)d_in[18];
    const float* dec_bfc   = (const float*)d_in[19];
    const int*   source    = (const int*)d_in[20];
    const int*   target    = (const int*)d_in[21];
    float* out = (float*)d_out;

    float* p_emb_s   = symaddr(g_emb_s);
    float* p_gi_f    = symaddr(g_gi_f);
    float* p_gi_b    = symaddr(g_gi_b);
    float* p_h       = symaddr(g_h);
    float* p_enc     = symaddr(g_enc);
    float* p_hfb     = symaddr(g_hfb);
    float* p_state   = symaddr(g_state);
    float* p_encproj = symaddr(g_encproj);

    static int attr_set = 0;
    if (!attr_set) {
        cudaFuncSetAttribute(k_logits_mma, cudaFuncAttributeMaxDynamicSharedMemorySize, LOG_SMEM);
        attr_set = 1;
    }

    // split dec_Wfc into bf16 hi/lo (independent of everything else)
    k_split_w<<<(NP*KP + 255)/256, 256>>>(dec_Wfc);

    // init h = 0 (both dirs, both parities)
    k_zero<<<(2*2*BB*UU + 255)/256, 256>>>(p_h, 2*2*BB*UU);

    // gather source embeddings
    k_gather_src<<<(SS*BB*EE + 255)/256, 256>>>(emb_src, source);

    // gi_f / gi_b : (2048 x 300) @ (300 x 1536)^T + bih
    {
        dim3 grid(GG/128, (SS*BB)/128);
        k_gemm<<<grid, 256>>>(p_emb_s, EE, enc_Wih_f, EE, 0, enc_bih_f,
                              p_gi_f, GG, SS*BB, GG, EE, 0);
        k_gemm<<<grid, 256>>>(p_emb_s, EE, enc_Wih_b, EE, 0, enc_bih_b,
                              p_gi_b, GG, SS*BB, GG, EE, 0);
    }

    // encoder recurrence
    for (int i = 0; i < SS; i++) {
        int par = i & 1;
        dim3 grid(GG/64, 4, 2);
        k_enc_gh<<<grid, 256>>>(enc_Whh_f, enc_Whh_b, par);
        k_enc_gate<<<(2*BB*UU)/256, 256>>>(i, SS-1-i, par, enc_bhh_f, enc_bhh_b);
    }

    k_concat_enc<<<(BB*SS*H2 + 255)/256, 256>>>();
    k_concat_hfb<<<(BB*H2 + 255)/256, 256>>>();

    // decoder init state
    {
        dim3 grid((UU + 127)/128, 1);
        k_gemm<<<grid, 256>>>(p_hfb, H2, enc_Wfc, H2, 0, enc_bfc,
                              p_state, UU, BB, UU, H2, 1);
    }

    // enc_proj = enc_bt @ attn_W[:, U:3U]^T + attn_b
    {
        dim3 grid(AD/128, (BB*SS)/128);
        k_gemm<<<grid, 256>>>(p_enc, H2, attn_W, GG, UU, attn_b,
                              p_encproj, AD, BB*SS, AD, H2, 0);
    }

    k_gather_trg<<<(TM1*BB*EE + 255)/256, 256>>>(emb_trg, target);

    // decoder recurrence
    for (int t = 0; t < TM1; t++) {
        int spar = t & 1;
        k_dec_attn<<<BB, 256>>>(spar, attn_W);
        dim3 grid(GG/64, 4, 2);
        k_dec_gemm<<<grid, 256>>>(spar, t, dec_Wih, dec_Whh);
        k_dec_gate<<<(BB*FF + 255)/256, 256>>>(spar, t, dec_bih, dec_bhh);
    }

    // split features into bf16 hi/lo
    k_split_a<<<(MP*KP + 255)/256, 256>>>();

    // output row 0 = zeros
    k_zero<<<(BB*VTT + 255)/256, 256>>>(out, BB*VTT);

    // logits on tensor cores (mma.sync bf16, split hi/lo): rows 1..31 of out
    {
        dim3 grid(MP/128, NP/128);
        k_logits_mma<<<grid, 256, LOG_SMEM>>>(dec_bfc, out + (long)BB*VTT);
    }
}